// round 3
// baseline (speedup 1.0000x reference)
#include <cuda_runtime.h>
#include <math.h>

#define NF   24
#define FS   8
#define DY   32
#define DX   32
#define SEQL 300
#define TOTAL (NF*FS*DY*DX*SEQL)   // 58,982,400 floats
#define N4    (TOTAL/4)            // 14,745,600 float4
#define ROW4  (SEQL/4)             // 75

#define A_THREADS 256
#define A_ILP     4
#define A_BLOCKS  (N4 / (A_THREADS * A_ILP))   // 14400 exactly

// Pass B: one thread per (position, lane) element.
#define B_POS     (NF * FS * 16 * 10)          // 30720 positions
#define B_THREADS 256
#define B_BLOCKS  (B_POS * 128 / B_THREADS)    // 15360

__device__ float g_max;   // global max of input; reset to 0 via memset each replay

__constant__ double c_lefts[NF] = {
    0.05, 0.0717, 0.0935, 0.1152, 0.137, 0.1587, 0.1804, 0.2022,
    0.2239, 0.2457, 0.2674, 0.2891, 0.3109, 0.3326, 0.3543, 0.3761,
    0.3978, 0.4196, 0.4413, 0.463, 0.4848, 0.5065, 0.5283, 0.55
};

// selected token: s==2 || s==3 || 9<=s<=108
__device__ __forceinline__ bool sel_tok(int s) {
    return ((unsigned)(s - 9) < 100u) || ((s & ~1) == 2);
}

// Pass A: out = in * (sel ? 0.918 : 1.0) everywhere + grid max of input.
// 4 independent LDG.128 issued up front per thread, exact-size grid.
__global__ void __launch_bounds__(A_THREADS)
apply_weaken_max(const float4* __restrict__ in, float4* __restrict__ out) {
    const int t      = blockIdx.x * A_THREADS + threadIdx.x;
    const int stride = A_BLOCKS * A_THREADS;

    int    idx[A_ILP];
    float4 v[A_ILP];
    #pragma unroll
    for (int k = 0; k < A_ILP; k++) { idx[k] = t + k * stride; }
    #pragma unroll
    for (int k = 0; k < A_ILP; k++) { v[k] = in[idx[k]]; }

    float mx = 0.f;
    #pragma unroll
    for (int k = 0; k < A_ILP; k++) {
        float4 x = v[k];
        mx = fmaxf(mx, fmaxf(fmaxf(x.x, x.y), fmaxf(x.z, x.w)));
        int s0 = (idx[k] % ROW4) * 4;
        float4 o;
        o.x = sel_tok(s0    ) ? x.x * 0.918f : x.x;
        o.y = sel_tok(s0 + 1) ? x.y * 0.918f : x.y;
        o.z = sel_tok(s0 + 2) ? x.z * 0.918f : x.z;
        o.w = sel_tok(s0 + 3) ? x.w * 0.918f : x.w;
        out[idx[k]] = o;
    }

    #pragma unroll
    for (int off = 16; off; off >>= 1)
        mx = fmaxf(mx, __shfl_xor_sync(0xffffffffu, mx, off));
    __shared__ float sm[A_THREADS / 32];
    if ((threadIdx.x & 31) == 0) sm[threadIdx.x >> 5] = mx;
    __syncthreads();
    if (threadIdx.x < (A_THREADS / 32)) {
        mx = sm[threadIdx.x];
        #pragma unroll
        for (int off = (A_THREADS / 64); off; off >>= 1)
            mx = fmaxf(mx, __shfl_xor_sync(0xffffffffu, mx, off));
        if (threadIdx.x == 0)
            atomicMax((int*)&g_max, __float_as_int(mx));   // inputs >= 0
    }
}

// Pass B: one thread per bbox element. Inside the bbox the gaussian is > 0,
// so the update is always: out = in + 0.125 * (patch/norm) * g_max.
// patch/norm computed as a single expf of the argument difference.
__global__ void __launch_bounds__(B_THREADS)
apply_strengthen(const float* __restrict__ in, float* __restrict__ out) {
    const int gid  = blockIdx.x * B_THREADS + threadIdx.x;
    const int lane = gid & 127;
    if (lane >= 102) return;
    int pos  = gid >> 7;                 // [0, 30720)
    const int xoff = pos % 10;  pos /= 10;
    const int yrow = pos & 15;  pos >>= 4;   // pos now = f*8+fs in [0,192)
    const int f    = pos >> 3;

    // bbox (Python int()/round() semantics in double)
    double l = c_lefts[f];
    double r = rint((l + 0.3) * 10000.0) / 10000.0;
    const int left = (int)((double)DX * l);
    const int w    = (int)((double)DX * r) - left;   // 9 or 10
    if (xoff >= w) return;
    const int h = 16;                                 // 24 - 8

    // Gaussian grid coords: x_i = i*h/(h-1), y_j = j*w/(w-1); center h//2, w//2.
    const float xstep = (float)h / (float)(h - 1);
    const float ystep = (float)w / (float)(w - 1);
    const float sx = (float)h / 3.0f, sy = (float)w / 3.0f;
    const float cx = (float)(h / 2),  cy = (float)(w / 2);

    float dx = (float)yrow * xstep - cx;
    float dy = (float)xoff * ystep - cy;

    // distance of nearest grid point to the center along each axis
    float dxmin = 1e30f, dymin = 1e30f;
    #pragma unroll
    for (int i = 0; i < h; i++) dxmin = fminf(dxmin, fabsf((float)i * xstep - cx));
    #pragma unroll 10
    for (int j = 0; j < 10; j++)
        if (j < w) dymin = fminf(dymin, fabsf((float)j * ystep - cy));

    const float inv2sx2 = 1.0f / (2.f * sx * sx);
    const float inv2sy2 = 1.0f / (2.f * sy * sy);
    // patch/norm = exp(-(dx^2 - dxmin^2)/(2sx^2) - (dy^2 - dymin^2)/(2sy^2))
    float g = expf((dxmin * dxmin - dx * dx) * inv2sx2 +
                   (dymin * dymin - dy * dy) * inv2sy2);

    const float wm = g * g_max;          // INJECTION_SCALE = 1.0
    const int tok = (lane < 2) ? (lane + 2) : (lane + 7);   // {2,3}, 9..108
    const int row = (pos * DY + 8 + yrow) * DX + (left + xoff);
    const int addr = row * SEQL + tok;
    out[addr] = in[addr] + 0.125f * wm;
}

extern "C" void kernel_launch(void* const* d_in, const int* in_sizes, int n_in,
                              void* d_out, int out_size) {
    const float* in = (const float*)d_in[0];
    float* out = (float*)d_out;

    static void* gmax_addr = nullptr;
    if (!gmax_addr) cudaGetSymbolAddress(&gmax_addr, g_max);

    cudaMemsetAsync(gmax_addr, 0, sizeof(float));
    apply_weaken_max<<<A_BLOCKS, A_THREADS>>>((const float4*)in, (float4*)out);
    apply_strengthen<<<B_BLOCKS, B_THREADS>>>(in, out);
}

// round 4
// speedup vs baseline: 2.1252x; 2.1252x over previous
#include <cuda_runtime.h>
#include <math.h>

#define NF   24
#define FS   8
#define DY   32
#define DX   32
#define SEQL 300
#define TOTAL (NF*FS*DY*DX*SEQL)   // 58,982,400 floats
#define N4    (TOTAL/4)            // 14,745,600 float4
#define ROW4  (SEQL/4)             // 75

#define A_THREADS 256
#define A_ILP     4
#define A_BLOCKS  (N4 / (A_THREADS * A_ILP))   // 14400 exactly

#define B_THREADS 256
#define B_BLOCKS  (NF * FS * 16 * 10 * 128 / B_THREADS)   // 15360

__device__ float g_max;   // global max of input; reset to 0 via memset each replay

// Hand-evaluated Python bbox math:
//   left  = int(32 * l)
//   right = int(32 * round(l + 0.3, 4)),  w = right - left
__constant__ int c_left[NF] = {
    1, 2, 2, 3, 4, 5, 5, 6, 7, 7, 8, 9,
    9, 10, 11, 12, 12, 13, 14, 14, 15, 16, 16, 17
};
__constant__ int c_w[NF] = {
    10, 9, 10, 10, 9, 9, 10, 10, 9, 10, 10, 9,
    10, 10, 9, 9, 10, 10, 9, 10, 10, 9, 10, 10
};

// selected token: s==2 || s==3 || 9<=s<=108
__device__ __forceinline__ bool sel_tok(int s) {
    return ((unsigned)(s - 9) < 100u) || ((s & ~1) == 2);
}

// Pass A: out = in * (sel ? 0.918 : 1.0) everywhere + grid max of input.
__global__ void __launch_bounds__(A_THREADS)
apply_weaken_max(const float4* __restrict__ in, float4* __restrict__ out) {
    const int t      = blockIdx.x * A_THREADS + threadIdx.x;
    const int stride = A_BLOCKS * A_THREADS;

    int    idx[A_ILP];
    float4 v[A_ILP];
    #pragma unroll
    for (int k = 0; k < A_ILP; k++) { idx[k] = t + k * stride; }
    #pragma unroll
    for (int k = 0; k < A_ILP; k++) { v[k] = in[idx[k]]; }

    float mx = 0.f;
    #pragma unroll
    for (int k = 0; k < A_ILP; k++) {
        float4 x = v[k];
        mx = fmaxf(mx, fmaxf(fmaxf(x.x, x.y), fmaxf(x.z, x.w)));
        int s0 = (idx[k] % ROW4) * 4;
        float4 o;
        o.x = sel_tok(s0    ) ? x.x * 0.918f : x.x;
        o.y = sel_tok(s0 + 1) ? x.y * 0.918f : x.y;
        o.z = sel_tok(s0 + 2) ? x.z * 0.918f : x.z;
        o.w = sel_tok(s0 + 3) ? x.w * 0.918f : x.w;
        out[idx[k]] = o;
    }

    #pragma unroll
    for (int off = 16; off; off >>= 1)
        mx = fmaxf(mx, __shfl_xor_sync(0xffffffffu, mx, off));
    __shared__ float sm[A_THREADS / 32];
    if ((threadIdx.x & 31) == 0) sm[threadIdx.x >> 5] = mx;
    __syncthreads();
    if (threadIdx.x < (A_THREADS / 32)) {
        mx = sm[threadIdx.x];
        #pragma unroll
        for (int off = (A_THREADS / 64); off; off >>= 1)
            mx = fmaxf(mx, __shfl_xor_sync(0xffffffffu, mx, off));
        if (threadIdx.x == 0)
            atomicMax((int*)&g_max, __float_as_int(mx));   // inputs >= 0
    }
}

// Pass B: one thread per bbox element; pure fp32, one __expf, one LDG, one STG.
// patch/norm = exp((dxmin^2-dx^2)/(2sx^2) + (dymin^2-dy^2)/(2sy^2))
//   h=16: xstep=16/15, cx=8, dxmin=8/15, 1/(2sx^2)=9/512
//   w=10: ystep=10/9, cy=5, dymin=5/9,  1/(2sy^2)=9/200
//   w=9 : ystep=9/8,  cy=4, dymin=1/2,  1/(2sy^2)=1/18
__global__ void __launch_bounds__(B_THREADS)
apply_strengthen(const float* __restrict__ in, float* __restrict__ out) {
    const int gid  = blockIdx.x * B_THREADS + threadIdx.x;
    const int lane = gid & 127;
    if (lane >= 102) return;
    int pos  = gid >> 7;                 // [0, 30720)
    const int xoff = pos % 10;  pos /= 10;
    const int yrow = pos & 15;  pos >>= 4;   // pos = f*8+fs in [0,192)
    const int f    = pos >> 3;

    const int w = c_w[f];
    if (xoff >= w) return;

    const float dx = (float)yrow * (16.0f / 15.0f) - 8.0f;
    const float dxmin = 8.0f / 15.0f;
    float ax = (dxmin * dxmin - dx * dx) * (9.0f / 512.0f);

    float dy, dymin2, inv2sy2;
    if (w == 10) {
        dy = (float)xoff * (10.0f / 9.0f) - 5.0f;
        dymin2 = (5.0f / 9.0f) * (5.0f / 9.0f);
        inv2sy2 = 9.0f / 200.0f;
    } else {
        dy = (float)xoff * (9.0f / 8.0f) - 4.0f;
        dymin2 = 0.25f;
        inv2sy2 = 1.0f / 18.0f;
    }
    float ay = (dymin2 - dy * dy) * inv2sy2;

    const float g = __expf(ax + ay);     // in (0,1], >0 inside bbox

    const int tok = (lane < 2) ? (lane + 2) : (lane + 7);   // {2,3}, 9..108
    const int row = (pos * DY + 8 + yrow) * DX + (c_left[f] + xoff);
    const int addr = row * SEQL + tok;
    out[addr] = in[addr] + 0.125f * g * g_max;
}

extern "C" void kernel_launch(void* const* d_in, const int* in_sizes, int n_in,
                              void* d_out, int out_size) {
    const float* in = (const float*)d_in[0];
    float* out = (float*)d_out;

    static void* gmax_addr = nullptr;
    if (!gmax_addr) cudaGetSymbolAddress(&gmax_addr, g_max);

    cudaMemsetAsync(gmax_addr, 0, sizeof(float));
    apply_weaken_max<<<A_BLOCKS, A_THREADS>>>((const float4*)in, (float4*)out);
    apply_strengthen<<<B_BLOCKS, B_THREADS>>>(in, out);
}

// round 5
// speedup vs baseline: 2.2391x; 1.0536x over previous
#include <cuda_runtime.h>
#include <math.h>

#define NF   24
#define FS   8
#define DY   32
#define DX   32
#define SEQL 300
#define TOTAL (NF*FS*DY*DX*SEQL)   // 58,982,400 floats
#define N4    (TOTAL/4)            // 14,745,600 float4
#define ROW4  (SEQL/4)             // 75

#define A_THREADS 256
#define A_ILP     4
#define A_BLOCKS  (N4 / (A_THREADS * A_ILP))   // 14400 exactly

#define B_POS     (NF * FS * 16 * 10)          // 30720 positions, 1 warp each
#define B_THREADS 256
#define B_BLOCKS  (B_POS / (B_THREADS / 32))   // 3840

__device__ float g_max;   // global max of input; reset to 0 via memset each replay

// Hand-evaluated Python bbox math: left = int(32*l), w = int(32*round(l+0.3,4)) - left
__constant__ int c_left[NF] = {
    1, 2, 2, 3, 4, 5, 5, 6, 7, 7, 8, 9,
    9, 10, 11, 12, 12, 13, 14, 14, 15, 16, 16, 17
};
__constant__ int c_w[NF] = {
    10, 9, 10, 10, 9, 9, 10, 10, 9, 10, 10, 9,
    10, 10, 9, 9, 10, 10, 9, 10, 10, 9, 10, 10
};

// selected token: s==2 || s==3 || 9<=s<=108
__device__ __forceinline__ bool sel_tok(int s) {
    return ((unsigned)(s - 9) < 100u) || ((s & ~1) == 2);
}

// Pass A: out = in * (sel ? 0.918 : 1.0) everywhere + grid max of input.
__global__ void __launch_bounds__(A_THREADS)
apply_weaken_max(const float4* __restrict__ in, float4* __restrict__ out) {
    const int t      = blockIdx.x * A_THREADS + threadIdx.x;
    const int stride = A_BLOCKS * A_THREADS;

    int    idx[A_ILP];
    float4 v[A_ILP];
    #pragma unroll
    for (int k = 0; k < A_ILP; k++) { idx[k] = t + k * stride; }
    #pragma unroll
    for (int k = 0; k < A_ILP; k++) { v[k] = in[idx[k]]; }

    float mx = 0.f;
    #pragma unroll
    for (int k = 0; k < A_ILP; k++) {
        float4 x = v[k];
        mx = fmaxf(mx, fmaxf(fmaxf(x.x, x.y), fmaxf(x.z, x.w)));
        int s0 = (idx[k] % ROW4) * 4;
        float4 o;
        o.x = sel_tok(s0    ) ? x.x * 0.918f : x.x;
        o.y = sel_tok(s0 + 1) ? x.y * 0.918f : x.y;
        o.z = sel_tok(s0 + 2) ? x.z * 0.918f : x.z;
        o.w = sel_tok(s0 + 3) ? x.w * 0.918f : x.w;
        out[idx[k]] = o;
    }

    #pragma unroll
    for (int off = 16; off; off >>= 1)
        mx = fmaxf(mx, __shfl_xor_sync(0xffffffffu, mx, off));
    __shared__ float sm[A_THREADS / 32];
    if ((threadIdx.x & 31) == 0) sm[threadIdx.x >> 5] = mx;
    __syncthreads();
    if (threadIdx.x < (A_THREADS / 32)) {
        mx = sm[threadIdx.x];
        #pragma unroll
        for (int off = (A_THREADS / 64); off; off >>= 1)
            mx = fmaxf(mx, __shfl_xor_sync(0xffffffffu, mx, off));
        if (threadIdx.x == 0)
            atomicMax((int*)&g_max, __float_as_int(mx));   // inputs >= 0
    }
}

// Pass B: one WARP per bbox spatial position; each lane covers tokens
// e = lane, lane+32, lane+64, lane+96 (e < 102). Per-position math amortized,
// 4 independent LDG/STG pairs per lane, coalesced across lanes.
__global__ void __launch_bounds__(B_THREADS)
apply_strengthen(const float* __restrict__ in, float* __restrict__ out) {
    const int wid  = (blockIdx.x * B_THREADS + threadIdx.x) >> 5;  // position id
    const int lane = threadIdx.x & 31;

    int pos = wid;
    const int xoff = pos % 10;  pos /= 10;
    const int yrow = pos & 15;  pos >>= 4;   // pos = f*8+fs in [0,192)
    const int f    = pos >> 3;

    const int w = c_w[f];
    if (xoff >= w) return;                   // warp-uniform exit

    // normalized gaussian (fp32, one MUFU):
    //   h=16: dx = yrow*16/15 - 8, dxmin = 8/15, 1/(2sx^2) = 9/512
    //   w=10: dy = xoff*10/9 - 5, dymin = 5/9,  1/(2sy^2) = 9/200
    //   w=9 : dy = xoff*9/8  - 4, dymin = 1/2,  1/(2sy^2) = 1/18
    const float dx = (float)yrow * (16.0f / 15.0f) - 8.0f;
    float ax = ((8.0f / 15.0f) * (8.0f / 15.0f) - dx * dx) * (9.0f / 512.0f);
    float dy, dymin2, inv2sy2;
    if (w == 10) {
        dy = (float)xoff * (10.0f / 9.0f) - 5.0f;
        dymin2 = (5.0f / 9.0f) * (5.0f / 9.0f);
        inv2sy2 = 9.0f / 200.0f;
    } else {
        dy = (float)xoff * (9.0f / 8.0f) - 4.0f;
        dymin2 = 0.25f;
        inv2sy2 = 1.0f / 18.0f;
    }
    const float add = 0.125f * __expf(ax + (dymin2 - dy * dy) * inv2sy2) * g_max;

    const int row  = (pos * DY + 8 + yrow) * DX + (c_left[f] + xoff);
    const float* ip = in  + row * SEQL;
    float*       op = out + row * SEQL;

    // tokens: e<2 -> e+2, else e+7
    int   tok[4];
    float v[4];
    #pragma unroll
    for (int k = 0; k < 4; k++) {
        int e = lane + 32 * k;
        tok[k] = (e < 2) ? (e + 2) : (e + 7);
        if (e < 102) v[k] = ip[tok[k]];
    }
    #pragma unroll
    for (int k = 0; k < 4; k++) {
        int e = lane + 32 * k;
        if (e < 102) op[tok[k]] = v[k] + add;
    }
}

extern "C" void kernel_launch(void* const* d_in, const int* in_sizes, int n_in,
                              void* d_out, int out_size) {
    const float* in = (const float*)d_in[0];
    float* out = (float*)d_out;

    static void* gmax_addr = nullptr;
    if (!gmax_addr) cudaGetSymbolAddress(&gmax_addr, g_max);

    cudaMemsetAsync(gmax_addr, 0, sizeof(float));
    apply_weaken_max<<<A_BLOCKS, A_THREADS>>>((const float4*)in, (float4*)out);
    apply_strengthen<<<B_BLOCKS, B_THREADS>>>(in, out);
}

// round 6
// speedup vs baseline: 2.3096x; 1.0315x over previous
#include <cuda_runtime.h>
#include <math.h>

#define NF   24
#define FS   8
#define DY   32
#define DX   32
#define SEQL 300
#define TOTAL (NF*FS*DY*DX*SEQL)   // 58,982,400 floats
#define N4    (TOTAL/4)            // 14,745,600 float4
#define ROW4  (SEQL/4)             // 75

#define A_THREADS 256
#define A_ILP     4
#define A_BLOCKS  (N4 / (A_THREADS * A_ILP))   // 14400 exactly
// stride = A_BLOCKS*A_THREADS = 3,686,400 = 75 * 49152  -> idx%75 invariant over ILP

#define B_POS     (NF * FS * 16 * 10)          // 30720 positions, 1 warp each
#define B_THREADS 256
#define B_BLOCKS  (B_POS / (B_THREADS / 32))   // 3840

__device__ float g_max;   // global max of input; reset to 0 via memset each replay

// Hand-evaluated Python bbox math: left = int(32*l), w = int(32*round(l+0.3,4)) - left
__constant__ int c_left[NF] = {
    1, 2, 2, 3, 4, 5, 5, 6, 7, 7, 8, 9,
    9, 10, 11, 12, 12, 13, 14, 14, 15, 16, 16, 17
};
__constant__ int c_w[NF] = {
    10, 9, 10, 10, 9, 9, 10, 10, 9, 10, 10, 9,
    10, 10, 9, 9, 10, 10, 9, 10, 10, 9, 10, 10
};

// selected token: s==2 || s==3 || 9<=s<=108
__device__ __forceinline__ bool sel_tok(int s) {
    return ((unsigned)(s - 9) < 100u) || ((s & ~1) == 2);
}

// Pass A: out = in * (sel ? 0.918 : 1.0) + grid max. Streaming (evict-first)
// loads/stores; seq position (and thus all multipliers) ILP-invariant.
__global__ void __launch_bounds__(A_THREADS)
apply_weaken_max(const float4* __restrict__ in, float4* __restrict__ out) {
    const int t      = blockIdx.x * A_THREADS + threadIdx.x;
    const int stride = A_BLOCKS * A_THREADS;

    const int s0 = (t % ROW4) * 4;     // same for all ILP slots
    float4 m;                           // per-component multipliers
    m.x = sel_tok(s0    ) ? 0.918f : 1.0f;
    m.y = sel_tok(s0 + 1) ? 0.918f : 1.0f;
    m.z = sel_tok(s0 + 2) ? 0.918f : 1.0f;
    m.w = sel_tok(s0 + 3) ? 0.918f : 1.0f;

    float4 v[A_ILP];
    #pragma unroll
    for (int k = 0; k < A_ILP; k++) v[k] = __ldcs(in + t + k * stride);

    float mx = 0.f;
    #pragma unroll
    for (int k = 0; k < A_ILP; k++) {
        float4 x = v[k];
        mx = fmaxf(mx, fmaxf(fmaxf(x.x, x.y), fmaxf(x.z, x.w)));
        float4 o = make_float4(x.x * m.x, x.y * m.y, x.z * m.z, x.w * m.w);
        __stcs(out + t + k * stride, o);
    }

    #pragma unroll
    for (int off = 16; off; off >>= 1)
        mx = fmaxf(mx, __shfl_xor_sync(0xffffffffu, mx, off));
    __shared__ float sm[A_THREADS / 32];
    if ((threadIdx.x & 31) == 0) sm[threadIdx.x >> 5] = mx;
    __syncthreads();
    if (threadIdx.x < (A_THREADS / 32)) {
        mx = sm[threadIdx.x];
        #pragma unroll
        for (int off = (A_THREADS / 64); off; off >>= 1)
            mx = fmaxf(mx, __shfl_xor_sync(0xffffffffu, mx, off));
        if (threadIdx.x == 0)
            atomicMax((int*)&g_max, __float_as_int(mx));   // inputs >= 0
    }
}

// Pass B: one WARP per bbox spatial position. Token map:
//   k=0..2: tok = 9 + lane + 32k      (fully active, 9..104)
//   k=3   : lane<4 -> 105+lane ; lane==4,5 -> lane-2 ({2,3}) ; else inactive
__global__ void __launch_bounds__(B_THREADS)
apply_strengthen(const float* __restrict__ in, float* __restrict__ out) {
    const int wid  = (blockIdx.x * B_THREADS + threadIdx.x) >> 5;
    const int lane = threadIdx.x & 31;

    int pos = wid;
    const int xoff = pos % 10;  pos /= 10;
    const int yrow = pos & 15;  pos >>= 4;   // pos = f*8+fs in [0,192)
    const int f    = pos >> 3;

    const int w = c_w[f];
    if (xoff >= w) return;                   // warp-uniform

    // normalized gaussian, fp32, one MUFU
    const float dx = (float)yrow * (16.0f / 15.0f) - 8.0f;
    float ax = ((8.0f / 15.0f) * (8.0f / 15.0f) - dx * dx) * (9.0f / 512.0f);
    float dy, dymin2, inv2sy2;
    if (w == 10) {
        dy = (float)xoff * (10.0f / 9.0f) - 5.0f;
        dymin2 = (5.0f / 9.0f) * (5.0f / 9.0f);
        inv2sy2 = 9.0f / 200.0f;
    } else {
        dy = (float)xoff * (9.0f / 8.0f) - 4.0f;
        dymin2 = 0.25f;
        inv2sy2 = 1.0f / 18.0f;
    }
    const float add = 0.125f * __expf(ax + (dymin2 - dy * dy) * inv2sy2) * g_max;

    const int row  = (pos * DY + 8 + yrow) * DX + (c_left[f] + xoff);
    const float* ip = in  + row * SEQL;
    float*       op = out + row * SEQL;

    const int tok3 = (lane < 4) ? (105 + lane) : (lane - 2);   // valid for lane<6
    const bool act3 = (lane < 6);

    float v0 = ip[9 + lane];
    float v1 = ip[41 + lane];
    float v2 = ip[73 + lane];
    float v3 = act3 ? ip[tok3] : 0.f;

    op[9  + lane] = v0 + add;
    op[41 + lane] = v1 + add;
    op[73 + lane] = v2 + add;
    if (act3) op[tok3] = v3 + add;
}

extern "C" void kernel_launch(void* const* d_in, const int* in_sizes, int n_in,
                              void* d_out, int out_size) {
    const float* in = (const float*)d_in[0];
    float* out = (float*)d_out;

    static void* gmax_addr = nullptr;
    if (!gmax_addr) cudaGetSymbolAddress(&gmax_addr, g_max);

    cudaMemsetAsync(gmax_addr, 0, sizeof(float));
    apply_weaken_max<<<A_BLOCKS, A_THREADS>>>((const float4*)in, (float4*)out);
    apply_strengthen<<<B_BLOCKS, B_THREADS>>>(in, out);
}

// round 7
// speedup vs baseline: 2.3514x; 1.0181x over previous
#include <cuda_runtime.h>
#include <math.h>

#define NF   24
#define FS   8
#define DY   32
#define DX   32
#define SEQL 300
#define TOTAL (NF*FS*DY*DX*SEQL)   // 58,982,400 floats
#define N4    (TOTAL/4)            // 14,745,600 float4
#define ROW4  (SEQL/4)             // 75

#define A_THREADS 256
#define A_ILP     4
#define A_BLOCKS  (N4 / (A_THREADS * A_ILP))   // 14400
// stride = 3,686,400 = 75 * 49152 -> idx%75 invariant over ILP slots

// Pass B: one warp per (f, yrow, xoff, fs-half); each warp covers 4 fs rows.
#define B_WARPS   (NF * 16 * 10 * 2)           // 7680
#define B_THREADS 256
#define B_BLOCKS  (B_WARPS / (B_THREADS / 32)) // 960
#define FS_STRIDE (DY * DX * SEQL)             // 307200 floats between fs slices

__device__ float g_max;   // reset to 0 via memset each replay (inputs >= 0)

// Hand-evaluated Python bbox math: left = int(32*l), w = int(32*round(l+0.3,4)) - left
__constant__ int c_left[NF] = {
    1, 2, 2, 3, 4, 5, 5, 6, 7, 7, 8, 9,
    9, 10, 11, 12, 12, 13, 14, 14, 15, 16, 16, 17
};
__constant__ int c_w[NF] = {
    10, 9, 10, 10, 9, 9, 10, 10, 9, 10, 10, 9,
    10, 10, 9, 9, 10, 10, 9, 10, 10, 9, 10, 10
};
__constant__ int c_edge_tok[6] = {2, 3, 9, 10, 11, 108};

// selected token: s==2 || s==3 || 9<=s<=108
__device__ __forceinline__ bool sel_tok(int s) {
    return ((unsigned)(s - 9) < 100u) || ((s & ~1) == 2);
}

// Pass A (unchanged from R6): out = in * (sel ? 0.918 : 1.0) + grid max.
__global__ void __launch_bounds__(A_THREADS)
apply_weaken_max(const float4* __restrict__ in, float4* __restrict__ out) {
    const int t      = blockIdx.x * A_THREADS + threadIdx.x;
    const int stride = A_BLOCKS * A_THREADS;

    const int s0 = (t % ROW4) * 4;
    float4 m;
    m.x = sel_tok(s0    ) ? 0.918f : 1.0f;
    m.y = sel_tok(s0 + 1) ? 0.918f : 1.0f;
    m.z = sel_tok(s0 + 2) ? 0.918f : 1.0f;
    m.w = sel_tok(s0 + 3) ? 0.918f : 1.0f;

    float4 v[A_ILP];
    #pragma unroll
    for (int k = 0; k < A_ILP; k++) v[k] = __ldcs(in + t + k * stride);

    float mx = 0.f;
    #pragma unroll
    for (int k = 0; k < A_ILP; k++) {
        float4 x = v[k];
        mx = fmaxf(mx, fmaxf(fmaxf(x.x, x.y), fmaxf(x.z, x.w)));
        __stcs(out + t + k * stride,
               make_float4(x.x * m.x, x.y * m.y, x.z * m.z, x.w * m.w));
    }

    #pragma unroll
    for (int off = 16; off; off >>= 1)
        mx = fmaxf(mx, __shfl_xor_sync(0xffffffffu, mx, off));
    __shared__ float sm[A_THREADS / 32];
    if ((threadIdx.x & 31) == 0) sm[threadIdx.x >> 5] = mx;
    __syncthreads();
    if (threadIdx.x < (A_THREADS / 32)) {
        mx = sm[threadIdx.x];
        #pragma unroll
        for (int off = (A_THREADS / 64); off; off >>= 1)
            mx = fmaxf(mx, __shfl_xor_sync(0xffffffffu, mx, off));
        if (threadIdx.x == 0)
            atomicMax((int*)&g_max, __float_as_int(mx));
    }
}

// Pass B: warp covers 4 fs-rows of one spatial position.
//   lane < 24 : float4 at tok 12+4*lane (16B-aligned: row*300 = 0 mod 4)
//   lane 24-29: scalar edge tokens {2,3,9,10,11,108}
__global__ void __launch_bounds__(B_THREADS)
apply_strengthen(const float* __restrict__ in, float* __restrict__ out) {
    const int W    = (blockIdx.x * B_THREADS + threadIdx.x) >> 5;
    const int lane = threadIdx.x & 31;

    const int half = W & 1;               // fs in {half*4 .. half*4+3}
    int pos = W >> 1;                      // [0, 3840)
    const int xoff = pos % 10;  pos /= 10;
    const int yrow = pos & 15;
    const int f    = pos >> 4;

    const int w = c_w[f];
    if (xoff >= w) return;                 // warp-uniform

    // normalized gaussian, fp32, one MUFU
    const float dx = (float)yrow * (16.0f / 15.0f) - 8.0f;
    float ax = ((8.0f / 15.0f) * (8.0f / 15.0f) - dx * dx) * (9.0f / 512.0f);
    float dy, dymin2, inv2sy2;
    if (w == 10) {
        dy = (float)xoff * (10.0f / 9.0f) - 5.0f;
        dymin2 = (5.0f / 9.0f) * (5.0f / 9.0f);
        inv2sy2 = 9.0f / 200.0f;
    } else {
        dy = (float)xoff * (9.0f / 8.0f) - 4.0f;
        dymin2 = 0.25f;
        inv2sy2 = 1.0f / 18.0f;
    }
    const float add = 0.125f * __expf(ax + (dymin2 - dy * dy) * inv2sy2) * g_max;

    // base element index of first row (fs = half*4)
    const long base = (long)((f * FS + half * 4) * DY + 8 + yrow) * DX * SEQL
                    + (long)(c_left[f] + xoff) * SEQL;

    if (lane < 24) {
        const int tok = 12 + 4 * lane;
        float4 v[4];
        #pragma unroll
        for (int r = 0; r < 4; r++)
            v[r] = *(const float4*)(in + base + (long)r * FS_STRIDE + tok);
        #pragma unroll
        for (int r = 0; r < 4; r++) {
            float4 o = make_float4(v[r].x + add, v[r].y + add,
                                   v[r].z + add, v[r].w + add);
            *(float4*)(out + base + (long)r * FS_STRIDE + tok) = o;
        }
    } else if (lane < 30) {
        const int tok = c_edge_tok[lane - 24];
        float v[4];
        #pragma unroll
        for (int r = 0; r < 4; r++)
            v[r] = in[base + (long)r * FS_STRIDE + tok];
        #pragma unroll
        for (int r = 0; r < 4; r++)
            out[base + (long)r * FS_STRIDE + tok] = v[r] + add;
    }
}

extern "C" void kernel_launch(void* const* d_in, const int* in_sizes, int n_in,
                              void* d_out, int out_size) {
    const float* in = (const float*)d_in[0];
    float* out = (float*)d_out;

    static void* gmax_addr = nullptr;
    if (!gmax_addr) cudaGetSymbolAddress(&gmax_addr, g_max);

    cudaMemsetAsync(gmax_addr, 0, sizeof(float));
    apply_weaken_max<<<A_BLOCKS, A_THREADS>>>((const float4*)in, (float4*)out);
    apply_strengthen<<<B_BLOCKS, B_THREADS>>>(in, out);
}